// round 1
// baseline (speedup 1.0000x reference)
#include <cuda_runtime.h>
#include <math.h>

#define BB 2
#define TT 2048
#define DD 1024
#define HH 16
#define HKD 64
#define HIDD 4096
#define BT (BB*TT)   // 4096 rows

// ---------------- scratch (static device allocations are allowed) ----------------
__device__ float g_xn [BB*TT*DD];
__device__ float g_y  [BB*TT*DD];
__device__ float g_q  [BB*TT*DD];
__device__ float g_k  [BB*TT*DD];
__device__ float g_v  [BB*TT*DD];
__device__ float g_ao [BB*TT*DD];
__device__ float g_x1 [BB*TT*DD];
__device__ float g_xn2[BB*TT*DD];
__device__ float g_hb [BB*TT*HIDD];

// ---------------- rmsnorm: one block per row of 1024 ----------------
__global__ void rmsnorm_kernel(const float* __restrict__ x, const float* __restrict__ g,
                               float* __restrict__ out)
{
    int row = blockIdx.x;
    int tid = threadIdx.x;                       // 256 threads, 4 floats each
    const float4* xr = (const float4*)(x + (size_t)row * DD);
    float4 v = xr[tid];
    float s = v.x*v.x + v.y*v.y + v.z*v.z + v.w*v.w;
    #pragma unroll
    for (int o = 16; o; o >>= 1) s += __shfl_xor_sync(0xffffffffu, s, o);
    __shared__ float red[8];
    if ((tid & 31) == 0) red[tid >> 5] = s;
    __syncthreads();
    float tot = red[0]+red[1]+red[2]+red[3]+red[4]+red[5]+red[6]+red[7];
    float inv = rsqrtf(tot * (1.0f / (float)DD) + 1e-6f);
    const float4* gr = (const float4*)g;
    float4 gv = gr[tid];
    float4 o4;
    o4.x = gv.x * (v.x * inv);
    o4.y = gv.y * (v.y * inv);
    o4.z = gv.z * (v.z * inv);
    o4.w = gv.w * (v.w * inv);
    ((float4*)(out + (size_t)row * DD))[tid] = o4;
}

// ---------------- EMA scan: one thread per (b,d,n); 16 lanes reduce over n ------
__global__ void ema_kernel(const float* __restrict__ xn,
                           const float* __restrict__ ap, const float* __restrict__ dp,
                           const float* __restrict__ beta, const float* __restrict__ eta,
                           float* __restrict__ y)
{
    int idx = blockIdx.x * blockDim.x + threadIdx.x;  // B*D*16 = 32768
    int n = idx & 15;
    int d = (idx >> 4) & (DD - 1);
    int b = idx >> 14;
    int dn = d * 16 + n;
    float a   = 1.0f / (1.0f + expf(-ap[dn]));
    float ddv = 1.0f / (1.0f + expf(-dp[dn]));
    float dec = 1.0f - a * ddv;
    float ab  = a * beta[dn];
    float et  = eta[dn];
    const float* xp = xn + (size_t)b * TT * DD + d;
    float* yp       = y  + (size_t)b * TT * DD + d;
    float h = 0.0f;
    for (int t = 0; t < TT; t++) {
        float u = xp[(size_t)t * DD];
        h = fmaf(dec, h, ab * u);
        float s = et * h;
        s += __shfl_xor_sync(0xffffffffu, s, 8, 16);
        s += __shfl_xor_sync(0xffffffffu, s, 4, 16);
        s += __shfl_xor_sync(0xffffffffu, s, 2, 16);
        s += __shfl_xor_sync(0xffffffffu, s, 1, 16);
        if (n == 0) yp[(size_t)t * DD] = s;
    }
}

// ---------------- RoPE (in-place on q,k,v), one thread per rotation pair --------
__global__ void rope_kernel(float* __restrict__ q, float* __restrict__ k, float* __restrict__ v)
{
    int idx = blockIdx.x * blockDim.x + threadIdx.x;   // B*T*H*16 = 2^20
    int i = idx & 15;
    int h = (idx >> 4) & 15;
    int t = (idx >> 8) & (TT - 1);
    int b = idx >> 19;
    double fd = pow(10000.0, -(double)i / 16.0);
    float freq = (float)fd;
    float ang = (float)t * freq;            // match jax fp32 angle
    double da = (double)ang;
    float c = (float)cos(da);
    float s = (float)sin(da);
    size_t base = ((size_t)(b * TT + t)) * DD + h * 64;
    {
        float x1 = q[base + i], x2 = q[base + 16 + i];
        q[base + i]      = x1 * c - x2 * s;
        q[base + 16 + i] = x2 * c + x1 * s;
    }
    {
        float x1 = k[base + i], x2 = k[base + 16 + i];
        k[base + i]      = x1 * c - x2 * s;
        k[base + 16 + i] = x2 * c + x1 * s;
    }
    {
        float x1 = v[base + i], x2 = v[base + 16 + i];
        v[base + i]      = x1 * c - x2 * s;
        v[base + 16 + i] = x2 * c + x1 * s;
    }
}

// ---------------- SGEMM 128x128x8, 256 threads, 8x8 per thread ------------------
// EPI: 0 = none, 1 = +resid, 2 = gelu(acc+bias), 3 = acc+bias+resid
__device__ __forceinline__ float gelu_tanh(float x)
{
    float x3 = x * x * x;
    float t = tanhf(0.7978845608028654f * (x + 0.044715f * x3));
    return 0.5f * x * (1.0f + t);
}

template<int EPI>
__global__ void sgemm_kernel(const float* __restrict__ A, const float* __restrict__ B,
                             float* __restrict__ C, const float* __restrict__ bias,
                             const float* __restrict__ resid, int M, int N, int K)
{
    __shared__ float As[8][132];
    __shared__ float Bs[8][128];
    const int tid = threadIdx.x;
    const int bx = blockIdx.x, by = blockIdx.y;
    const int arow = tid >> 1;
    const int acol = (tid & 1) << 2;
    const int brow = tid >> 5;
    const int bcol = (tid & 31) << 2;
    const float* Ap = A + (size_t)(by * 128 + arow) * K + acol;
    const float* Bp = B + (size_t)brow * N + bx * 128 + bcol;
    const int tx = tid & 15, ty = tid >> 4;

    float acc[8][8];
    #pragma unroll
    for (int i = 0; i < 8; i++)
        #pragma unroll
        for (int j = 0; j < 8; j++) acc[i][j] = 0.0f;

    for (int k0 = 0; k0 < K; k0 += 8) {
        float4 av = *(const float4*)Ap;  Ap += 8;
        float4 bv = *(const float4*)Bp;  Bp += (size_t)8 * N;
        __syncthreads();
        As[acol + 0][arow] = av.x;
        As[acol + 1][arow] = av.y;
        As[acol + 2][arow] = av.z;
        As[acol + 3][arow] = av.w;
        *(float4*)&Bs[brow][bcol] = bv;
        __syncthreads();
        #pragma unroll
        for (int kk = 0; kk < 8; kk++) {
            float4 a0 = *(const float4*)&As[kk][ty * 8];
            float4 a1 = *(const float4*)&As[kk][ty * 8 + 4];
            float4 b0 = *(const float4*)&Bs[kk][tx * 8];
            float4 b1 = *(const float4*)&Bs[kk][tx * 8 + 4];
            float ar[8] = {a0.x,a0.y,a0.z,a0.w,a1.x,a1.y,a1.z,a1.w};
            float br[8] = {b0.x,b0.y,b0.z,b0.w,b1.x,b1.y,b1.z,b1.w};
            #pragma unroll
            for (int i = 0; i < 8; i++)
                #pragma unroll
                for (int j = 0; j < 8; j++)
                    acc[i][j] = fmaf(ar[i], br[j], acc[i][j]);
        }
    }

    int row0 = by * 128 + ty * 8;
    int col0 = bx * 128 + tx * 8;
    #pragma unroll
    for (int i = 0; i < 8; i++) {
        size_t off = (size_t)(row0 + i) * N + col0;
        float vv[8];
        #pragma unroll
        for (int j = 0; j < 8; j++) {
            float t = acc[i][j];
            if (EPI == 2 || EPI == 3) t += bias[col0 + j];
            if (EPI == 2) t = gelu_tanh(t);
            if (EPI == 1 || EPI == 3) t += resid[off + j];
            vv[j] = t;
        }
        *(float4*)(C + off)     = make_float4(vv[0], vv[1], vv[2], vv[3]);
        *(float4*)(C + off + 4) = make_float4(vv[4], vv[5], vv[6], vv[7]);
    }
}

// ---------------- causal flash attention, fp32, BM=BN=64, d=64 ------------------
#define ATTN_SMEM_FLOATS (3*64*68 + 64*65)
#define ATTN_SMEM_BYTES  (ATTN_SMEM_FLOATS * 4)

__global__ void attn_kernel(const float* __restrict__ Q, const float* __restrict__ Kk,
                            const float* __restrict__ V, float* __restrict__ O)
{
    extern __shared__ float sm[];
    float* Qs = sm;                 // [64 dims][68] transposed : Qs[d*68 + r]
    float* Ks = sm + 64 * 68;       // [64 dims][68] transposed : Ks[d*68 + c]
    float* Vs = sm + 2 * 64 * 68;   // [64 rows][68] natural    : Vs[c*68 + d]
    float* Ps = sm + 3 * 64 * 68;   // [64 rows][65] natural    : Ps[r*65 + c]

    int qt = blockIdx.x;            // q tile (64 rows)
    int bh = blockIdx.y;
    int b = bh >> 4, h = bh & 15;
    const size_t ld = DD;
    const float* Qb = Q  + (size_t)b * TT * ld + h * 64;
    const float* Kb = Kk + (size_t)b * TT * ld + h * 64;
    const float* Vb = V  + (size_t)b * TT * ld + h * 64;
    float*       Ob = O  + (size_t)b * TT * ld + h * 64;

    int tid = threadIdx.x;          // 256
    int tx = tid & 15, ty = tid >> 4;

    // load Q tile transposed, folding in 1/sqrt(64)
    for (int i = tid; i < 64 * 16; i += 256) {
        int r = i >> 4, d4 = (i & 15) << 2;
        float4 qv = *(const float4*)(Qb + (size_t)(qt * 64 + r) * ld + d4);
        Qs[(d4 + 0) * 68 + r] = qv.x * 0.125f;
        Qs[(d4 + 1) * 68 + r] = qv.y * 0.125f;
        Qs[(d4 + 2) * 68 + r] = qv.z * 0.125f;
        Qs[(d4 + 3) * 68 + r] = qv.w * 0.125f;
    }

    float m_i[4], l_i[4], acc[4][4];
    #pragma unroll
    for (int i = 0; i < 4; i++) {
        m_i[i] = -1e30f; l_i[i] = 0.0f;
        #pragma unroll
        for (int j = 0; j < 4; j++) acc[i][j] = 0.0f;
    }

    for (int kt = 0; kt <= qt; kt++) {
        __syncthreads();     // K/V consumers of previous tile done (also covers Q store, 1st iter)
        for (int i = tid; i < 64 * 16; i += 256) {
            int c = i >> 4, d4 = (i & 15) << 2;
            float4 kv = *(const float4*)(Kb + (size_t)(kt * 64 + c) * ld + d4);
            Ks[(d4 + 0) * 68 + c] = kv.x;
            Ks[(d4 + 1) * 68 + c] = kv.y;
            Ks[(d4 + 2) * 68 + c] = kv.z;
            Ks[(d4 + 3) * 68 + c] = kv.w;
            float4 vv = *(const float4*)(Vb + (size_t)(kt * 64 + c) * ld + d4);
            *(float4*)&Vs[c * 68 + d4] = vv;
        }
        __syncthreads();

        float s[4][4];
        #pragma unroll
        for (int i = 0; i < 4; i++)
            #pragma unroll
            for (int j = 0; j < 4; j++) s[i][j] = 0.0f;

        #pragma unroll 16
        for (int kk = 0; kk < 64; kk++) {
            float4 qv = *(const float4*)&Qs[kk * 68 + ty * 4];
            float4 kv = *(const float4*)&Ks[kk * 68 + tx * 4];
            float qa[4] = {qv.x, qv.y, qv.z, qv.w};
            float ka[4] = {kv.x, kv.y, kv.z, kv.w};
            #pragma unroll
            for (int i = 0; i < 4; i++)
                #pragma unroll
                for (int j = 0; j < 4; j++)
                    s[i][j] = fmaf(qa[i], ka[j], s[i][j]);
        }

        if (kt == qt) {   // causal mask inside diagonal tile
            #pragma unroll
            for (int i = 0; i < 4; i++)
                #pragma unroll
                for (int j = 0; j < 4; j++)
                    if (tx * 4 + j > ty * 4 + i) s[i][j] = -1e30f;
        }

        #pragma unroll
        for (int i = 0; i < 4; i++) {
            float rm = fmaxf(fmaxf(s[i][0], s[i][1]), fmaxf(s[i][2], s[i][3]));
            rm = fmaxf(rm, __shfl_xor_sync(0xffffffffu, rm, 8, 16));
            rm = fmaxf(rm, __shfl_xor_sync(0xffffffffu, rm, 4, 16));
            rm = fmaxf(rm, __shfl_xor_sync(0xffffffffu, rm, 2, 16));
            rm = fmaxf(rm, __shfl_xor_sync(0xffffffffu, rm, 1, 16));
            float mn = fmaxf(m_i[i], rm);
            float alpha = __expf(m_i[i] - mn);
            m_i[i] = mn;
            float rs = 0.0f;
            #pragma unroll
            for (int j = 0; j < 4; j++) {
                float p = __expf(s[i][j] - mn);
                s[i][j] = p;
                rs += p;
            }
            rs += __shfl_xor_sync(0xffffffffu, rs, 8, 16);
            rs += __shfl_xor_sync(0xffffffffu, rs, 4, 16);
            rs += __shfl_xor_sync(0xffffffffu, rs, 2, 16);
            rs += __shfl_xor_sync(0xffffffffu, rs, 1, 16);
            l_i[i] = l_i[i] * alpha + rs;
            #pragma unroll
            for (int j = 0; j < 4; j++) acc[i][j] *= alpha;
            int r = ty * 4 + i;
            Ps[r * 65 + tx * 4 + 0] = s[i][0];
            Ps[r * 65 + tx * 4 + 1] = s[i][1];
            Ps[r * 65 + tx * 4 + 2] = s[i][2];
            Ps[r * 65 + tx * 4 + 3] = s[i][3];
        }
        __syncwarp();   // P rows for this ty are produced and consumed within one warp

        #pragma unroll 8
        for (int c = 0; c < 64; c++) {
            float4 vv = *(const float4*)&Vs[c * 68 + tx * 4];
            float va[4] = {vv.x, vv.y, vv.z, vv.w};
            float p0 = Ps[(ty * 4 + 0) * 65 + c];
            float p1 = Ps[(ty * 4 + 1) * 65 + c];
            float p2 = Ps[(ty * 4 + 2) * 65 + c];
            float p3 = Ps[(ty * 4 + 3) * 65 + c];
            #pragma unroll
            for (int j = 0; j < 4; j++) {
                acc[0][j] = fmaf(p0, va[j], acc[0][j]);
                acc[1][j] = fmaf(p1, va[j], acc[1][j]);
                acc[2][j] = fmaf(p2, va[j], acc[2][j]);
                acc[3][j] = fmaf(p3, va[j], acc[3][j]);
            }
        }
    }

    #pragma unroll
    for (int i = 0; i < 4; i++) {
        float inv = 1.0f / l_i[i];
        float4 o4 = make_float4(acc[i][0] * inv, acc[i][1] * inv,
                                acc[i][2] * inv, acc[i][3] * inv);
        *(float4*)(Ob + (size_t)(qt * 64 + ty * 4 + i) * ld + tx * 4) = o4;
    }
}

// ---------------- launch ----------------
extern "C" void kernel_launch(void* const* d_in, const int* in_sizes, int n_in,
                              void* d_out, int out_size)
{
    const float* x       = (const float*)d_in[0];
    const float* w_q     = (const float*)d_in[1];
    const float* w_k     = (const float*)d_in[2];
    const float* w_v     = (const float*)d_in[3];
    const float* w_o     = (const float*)d_in[4];
    const float* alpha_p = (const float*)d_in[5];
    const float* delta_p = (const float*)d_in[6];
    const float* beta    = (const float*)d_in[7];
    const float* eta     = (const float*)d_in[8];
    const float* g1      = (const float*)d_in[9];
    const float* g2      = (const float*)d_in[10];
    const float* w_in    = (const float*)d_in[11];
    const float* b_in    = (const float*)d_in[12];
    const float* w_out   = (const float*)d_in[13];
    const float* b_out   = (const float*)d_in[14];
    float* out = (float*)d_out;

    float *xn, *y, *q, *k, *v, *ao, *x1, *xn2, *hb;
    cudaGetSymbolAddress((void**)&xn,  g_xn);
    cudaGetSymbolAddress((void**)&y,   g_y);
    cudaGetSymbolAddress((void**)&q,   g_q);
    cudaGetSymbolAddress((void**)&k,   g_k);
    cudaGetSymbolAddress((void**)&v,   g_v);
    cudaGetSymbolAddress((void**)&ao,  g_ao);
    cudaGetSymbolAddress((void**)&x1,  g_x1);
    cudaGetSymbolAddress((void**)&xn2, g_xn2);
    cudaGetSymbolAddress((void**)&hb,  g_hb);

    cudaFuncSetAttribute(attn_kernel, cudaFuncAttributeMaxDynamicSharedMemorySize,
                         ATTN_SMEM_BYTES);

    // 1. xn = rmsnorm(x, g1)
    rmsnorm_kernel<<<BT, 256>>>(x, g1, xn);
    // 2. y = EMA(xn)
    ema_kernel<<<(BB * DD * 16) / 256, 256>>>(xn, alpha_p, delta_p, beta, eta, y);
    // 3. q/k/v projections
    dim3 gN1024(1024 / 128, BT / 128);
    sgemm_kernel<0><<<gN1024, 256>>>(y,  w_q, q, nullptr, nullptr, BT, 1024, 1024);
    sgemm_kernel<0><<<gN1024, 256>>>(y,  w_k, k, nullptr, nullptr, BT, 1024, 1024);
    sgemm_kernel<0><<<gN1024, 256>>>(xn, w_v, v, nullptr, nullptr, BT, 1024, 1024);
    // 4. rope on q,k,v
    rope_kernel<<<(BB * TT * HH * 16) / 256, 256>>>(q, k, v);
    // 5. causal attention
    attn_kernel<<<dim3(TT / 64, BB * HH), 256, ATTN_SMEM_BYTES>>>(q, k, v, ao);
    // 6. x1 = x + ao @ w_o
    sgemm_kernel<1><<<gN1024, 256>>>(ao, w_o, x1, nullptr, x, BT, 1024, 1024);
    // 7. xn2 = rmsnorm(x1, g2)
    rmsnorm_kernel<<<BT, 256>>>(x1, g2, xn2);
    // 8. hb = gelu(xn2 @ w_in + b_in)
    dim3 gN4096(4096 / 128, BT / 128);
    sgemm_kernel<2><<<gN4096, 256>>>(xn2, w_in, hb, b_in, nullptr, BT, 4096, 1024);
    // 9. out = x1 + hb @ w_out + b_out
    sgemm_kernel<3><<<gN1024, 256>>>(hb, w_out, out, b_out, x1, BT, 1024, 4096);
}

// round 2
// speedup vs baseline: 1.7970x; 1.7970x over previous
#include <cuda_runtime.h>
#include <math.h>

#define BB 2
#define TT 2048
#define DD 1024
#define HH 16
#define HIDD 4096
#define BT (BB*TT)   // 4096 rows

// ---------------- scratch ----------------
__device__ float g_xn [BB*TT*DD];
__device__ float g_y  [BB*TT*DD];
__device__ float g_q  [BB*TT*DD];
__device__ float g_k  [BB*TT*DD];
__device__ float g_v  [BB*TT*DD];
__device__ float g_ao [BB*TT*DD];
__device__ float g_x1 [BB*TT*DD];
__device__ float g_xn2[BB*TT*DD];
__device__ float g_hb [BB*TT*HIDD];

// ---------------- rmsnorm ----------------
__global__ void rmsnorm_kernel(const float* __restrict__ x, const float* __restrict__ g,
                               float* __restrict__ out)
{
    int row = blockIdx.x;
    int tid = threadIdx.x;
    const float4* xr = (const float4*)(x + (size_t)row * DD);
    float4 v = xr[tid];
    float s = v.x*v.x + v.y*v.y + v.z*v.z + v.w*v.w;
    #pragma unroll
    for (int o = 16; o; o >>= 1) s += __shfl_xor_sync(0xffffffffu, s, o);
    __shared__ float red[8];
    if ((tid & 31) == 0) red[tid >> 5] = s;
    __syncthreads();
    float tot = red[0]+red[1]+red[2]+red[3]+red[4]+red[5]+red[6]+red[7];
    float inv = rsqrtf(tot * (1.0f / (float)DD) + 1e-6f);
    const float4* gr = (const float4*)g;
    float4 gv = gr[tid];
    float4 o4;
    o4.x = gv.x * (v.x * inv);
    o4.y = gv.y * (v.y * inv);
    o4.z = gv.z * (v.z * inv);
    o4.w = gv.w * (v.w * inv);
    ((float4*)(out + (size_t)row * DD))[tid] = o4;
}

// ---------------- EMA scan ----------------
__global__ void ema_kernel(const float* __restrict__ xn,
                           const float* __restrict__ ap, const float* __restrict__ dp,
                           const float* __restrict__ beta, const float* __restrict__ eta,
                           float* __restrict__ y)
{
    int idx = blockIdx.x * blockDim.x + threadIdx.x;
    int n = idx & 15;
    int d = (idx >> 4) & (DD - 1);
    int b = idx >> 14;
    int dn = d * 16 + n;
    float a   = 1.0f / (1.0f + expf(-ap[dn]));
    float ddv = 1.0f / (1.0f + expf(-dp[dn]));
    float dec = 1.0f - a * ddv;
    float ab  = a * beta[dn];
    float et  = eta[dn];
    const float* xp = xn + (size_t)b * TT * DD + d;
    float* yp       = y  + (size_t)b * TT * DD + d;
    float h = 0.0f;
    for (int t = 0; t < TT; t++) {
        float u = xp[(size_t)t * DD];
        h = fmaf(dec, h, ab * u);
        float s = et * h;
        s += __shfl_xor_sync(0xffffffffu, s, 8, 16);
        s += __shfl_xor_sync(0xffffffffu, s, 4, 16);
        s += __shfl_xor_sync(0xffffffffu, s, 2, 16);
        s += __shfl_xor_sync(0xffffffffu, s, 1, 16);
        if (n == 0) yp[(size_t)t * DD] = s;
    }
}

// ---------------- RoPE ----------------
__global__ void rope_kernel(float* __restrict__ q, float* __restrict__ k, float* __restrict__ v)
{
    int idx = blockIdx.x * blockDim.x + threadIdx.x;
    int i = idx & 15;
    int h = (idx >> 4) & 15;
    int t = (idx >> 8) & (TT - 1);
    int b = idx >> 19;
    double fd = pow(10000.0, -(double)i / 16.0);
    float freq = (float)fd;
    float ang = (float)t * freq;
    double da = (double)ang;
    float c = (float)cos(da);
    float s = (float)sin(da);
    size_t base = ((size_t)(b * TT + t)) * DD + h * 64;
    {
        float x1 = q[base + i], x2 = q[base + 16 + i];
        q[base + i]      = x1 * c - x2 * s;
        q[base + 16 + i] = x2 * c + x1 * s;
    }
    {
        float x1 = k[base + i], x2 = k[base + 16 + i];
        k[base + i]      = x1 * c - x2 * s;
        k[base + 16 + i] = x2 * c + x1 * s;
    }
    {
        float x1 = v[base + i], x2 = v[base + 16 + i];
        v[base + i]      = x1 * c - x2 * s;
        v[base + 16 + i] = x2 * c + x1 * s;
    }
}

// ---------------- tf32 tensor-core GEMM 128x128x16 ----------------
__device__ __forceinline__ float gelu_tanh(float x)
{
    float x3 = x * x * x;
    float t = tanhf(0.7978845608028654f * (x + 0.044715f * x3));
    return 0.5f * x * (1.0f + t);
}

__device__ __forceinline__ unsigned f2tf32(float x)
{
    unsigned r;
    asm("cvt.rna.tf32.f32 %0, %1;" : "=r"(r) : "f"(x));
    return r;
}

__device__ __forceinline__ void mma_tf32(float* d, const unsigned* a, const unsigned* b)
{
    asm volatile(
        "mma.sync.aligned.m16n8k8.row.col.f32.tf32.tf32.f32 "
        "{%0,%1,%2,%3}, {%4,%5,%6,%7}, {%8,%9}, {%0,%1,%2,%3};\n"
        : "+f"(d[0]), "+f"(d[1]), "+f"(d[2]), "+f"(d[3])
        : "r"(a[0]), "r"(a[1]), "r"(a[2]), "r"(a[3]), "r"(b[0]), "r"(b[1]));
}

// EPI: 0 = none, 1 = +resid, 2 = gelu(acc+bias), 3 = acc+bias+resid
template<int EPI>
__global__ __launch_bounds__(256)
void tgemm_kernel(const float* __restrict__ A, const float* __restrict__ B,
                  float* __restrict__ C, const float* __restrict__ bias,
                  const float* __restrict__ resid, int M, int N, int K)
{
    __shared__ float As[2][16][132];   // [buf][k][m]
    __shared__ float Bs[2][16][132];   // [buf][k][n]

    const int tid  = threadIdx.x;
    const int bx = blockIdx.x, by = blockIdx.y;
    const int lane = tid & 31;
    const int warp = tid >> 5;
    const int wm = (warp & 1) * 64;    // warp m offset within block tile
    const int wn = (warp >> 1) * 32;   // warp n offset
    const int lr = lane >> 2;          // 0..7
    const int lc = lane & 3;           // 0..3

    // global load slots: A rows (tid>>2) and (tid>>2)+64, k cols (tid&3)*4..+3
    //                    B rows (tid>>5) and (tid>>5)+8,  n cols (tid&31)*4..+3
    const int am = tid >> 2;
    const int ak = (tid & 3) << 2;
    const int bk = tid >> 5;
    const int bn = (tid & 31) << 2;
    const float* Ap = A + (size_t)(by * 128 + am) * K + ak;
    const float* Bp = B + (size_t)bk * N + bx * 128 + bn;

    float4 a0g = *(const float4*)Ap;
    float4 a1g = *(const float4*)(Ap + (size_t)64 * K);
    float4 b0g = *(const float4*)Bp;
    float4 b1g = *(const float4*)(Bp + (size_t)8 * N);

    // store tile 0
    As[0][ak + 0][am] = a0g.x;
    As[0][ak + 1][am] = a0g.y;
    As[0][ak + 2][am] = a0g.z;
    As[0][ak + 3][am] = a0g.w;
    As[0][ak + 0][am + 64] = a1g.x;
    As[0][ak + 1][am + 64] = a1g.y;
    As[0][ak + 2][am + 64] = a1g.z;
    As[0][ak + 3][am + 64] = a1g.w;
    *(float4*)&Bs[0][bk][bn]     = b0g;
    *(float4*)&Bs[0][bk + 8][bn] = b1g;
    __syncthreads();

    float acc[4][4][4];
    #pragma unroll
    for (int mt = 0; mt < 4; mt++)
        #pragma unroll
        for (int nt = 0; nt < 4; nt++)
            #pragma unroll
            for (int r = 0; r < 4; r++) acc[mt][nt][r] = 0.0f;

    for (int k0 = 0; k0 < K; k0 += 16) {
        const int cb = (k0 >> 4) & 1;
        const bool has_next = (k0 + 16) < K;
        if (has_next) {
            Ap += 16;
            Bp += (size_t)16 * N;
            a0g = *(const float4*)Ap;
            a1g = *(const float4*)(Ap + (size_t)64 * K);
            b0g = *(const float4*)Bp;
            b1g = *(const float4*)(Bp + (size_t)8 * N);
        }

        #pragma unroll
        for (int s = 0; s < 2; s++) {
            const int kb = s * 8;
            unsigned af[4][4], bf[4][2];
            #pragma unroll
            for (int mt = 0; mt < 4; mt++) {
                int m = wm + mt * 16 + lr;
                af[mt][0] = f2tf32(As[cb][kb + lc][m]);
                af[mt][1] = f2tf32(As[cb][kb + lc][m + 8]);
                af[mt][2] = f2tf32(As[cb][kb + lc + 4][m]);
                af[mt][3] = f2tf32(As[cb][kb + lc + 4][m + 8]);
            }
            #pragma unroll
            for (int nt = 0; nt < 4; nt++) {
                int n = wn + nt * 8 + lr;
                bf[nt][0] = f2tf32(Bs[cb][kb + lc][n]);
                bf[nt][1] = f2tf32(Bs[cb][kb + lc + 4][n]);
            }
            #pragma unroll
            for (int mt = 0; mt < 4; mt++)
                #pragma unroll
                for (int nt = 0; nt < 4; nt++)
                    mma_tf32(acc[mt][nt], af[mt], bf[nt]);
        }

        if (has_next) {
            const int nb = cb ^ 1;
            As[nb][ak + 0][am] = a0g.x;
            As[nb][ak + 1][am] = a0g.y;
            As[nb][ak + 2][am] = a0g.z;
            As[nb][ak + 3][am] = a0g.w;
            As[nb][ak + 0][am + 64] = a1g.x;
            As[nb][ak + 1][am + 64] = a1g.y;
            As[nb][ak + 2][am + 64] = a1g.z;
            As[nb][ak + 3][am + 64] = a1g.w;
            *(float4*)&Bs[nb][bk][bn]     = b0g;
            *(float4*)&Bs[nb][bk + 8][bn] = b1g;
        }
        __syncthreads();
    }

    // epilogue: c0,c1 at (row, col..col+1); c2,c3 at (row+8, ...)
    #pragma unroll
    for (int mt = 0; mt < 4; mt++) {
        #pragma unroll
        for (int nt = 0; nt < 4; nt++) {
            int row = by * 128 + wm + mt * 16 + lr;
            int col = bx * 128 + wn + nt * 8 + 2 * lc;
            #pragma unroll
            for (int half = 0; half < 2; half++) {
                int r = row + half * 8;
                size_t off = (size_t)r * N + col;
                float v0 = acc[mt][nt][half * 2 + 0];
                float v1 = acc[mt][nt][half * 2 + 1];
                if (EPI == 2 || EPI == 3) { v0 += bias[col]; v1 += bias[col + 1]; }
                if (EPI == 2) { v0 = gelu_tanh(v0); v1 = gelu_tanh(v1); }
                if (EPI == 1 || EPI == 3) { v0 += resid[off]; v1 += resid[off + 1]; }
                *(float2*)(C + off) = make_float2(v0, v1);
            }
        }
    }
}

// ---------------- causal flash attention, fp32 ----------------
#define ATTN_SMEM_FLOATS (3*64*68 + 64*65)
#define ATTN_SMEM_BYTES  (ATTN_SMEM_FLOATS * 4)

__global__ void attn_kernel(const float* __restrict__ Q, const float* __restrict__ Kk,
                            const float* __restrict__ V, float* __restrict__ O)
{
    extern __shared__ float sm[];
    float* Qs = sm;
    float* Ks = sm + 64 * 68;
    float* Vs = sm + 2 * 64 * 68;
    float* Ps = sm + 3 * 64 * 68;

    int qt = blockIdx.x;
    int bh = blockIdx.y;
    int b = bh >> 4, h = bh & 15;
    const size_t ld = DD;
    const float* Qb = Q  + (size_t)b * TT * ld + h * 64;
    const float* Kb = Kk + (size_t)b * TT * ld + h * 64;
    const float* Vb = V  + (size_t)b * TT * ld + h * 64;
    float*       Ob = O  + (size_t)b * TT * ld + h * 64;

    int tid = threadIdx.x;
    int tx = tid & 15, ty = tid >> 4;

    for (int i = tid; i < 64 * 16; i += 256) {
        int r = i >> 4, d4 = (i & 15) << 2;
        float4 qv = *(const float4*)(Qb + (size_t)(qt * 64 + r) * ld + d4);
        Qs[(d4 + 0) * 68 + r] = qv.x * 0.125f;
        Qs[(d4 + 1) * 68 + r] = qv.y * 0.125f;
        Qs[(d4 + 2) * 68 + r] = qv.z * 0.125f;
        Qs[(d4 + 3) * 68 + r] = qv.w * 0.125f;
    }

    float m_i[4], l_i[4], acc[4][4];
    #pragma unroll
    for (int i = 0; i < 4; i++) {
        m_i[i] = -1e30f; l_i[i] = 0.0f;
        #pragma unroll
        for (int j = 0; j < 4; j++) acc[i][j] = 0.0f;
    }

    for (int kt = 0; kt <= qt; kt++) {
        __syncthreads();
        for (int i = tid; i < 64 * 16; i += 256) {
            int c = i >> 4, d4 = (i & 15) << 2;
            float4 kv = *(const float4*)(Kb + (size_t)(kt * 64 + c) * ld + d4);
            Ks[(d4 + 0) * 68 + c] = kv.x;
            Ks[(d4 + 1) * 68 + c] = kv.y;
            Ks[(d4 + 2) * 68 + c] = kv.z;
            Ks[(d4 + 3) * 68 + c] = kv.w;
            float4 vv = *(const float4*)(Vb + (size_t)(kt * 64 + c) * ld + d4);
            *(float4*)&Vs[c * 68 + d4] = vv;
        }
        __syncthreads();

        float s[4][4];
        #pragma unroll
        for (int i = 0; i < 4; i++)
            #pragma unroll
            for (int j = 0; j < 4; j++) s[i][j] = 0.0f;

        #pragma unroll 16
        for (int kk = 0; kk < 64; kk++) {
            float4 qv = *(const float4*)&Qs[kk * 68 + ty * 4];
            float4 kv = *(const float4*)&Ks[kk * 68 + tx * 4];
            float qa[4] = {qv.x, qv.y, qv.z, qv.w};
            float ka[4] = {kv.x, kv.y, kv.z, kv.w};
            #pragma unroll
            for (int i = 0; i < 4; i++)
                #pragma unroll
                for (int j = 0; j < 4; j++)
                    s[i][j] = fmaf(qa[i], ka[j], s[i][j]);
        }

        if (kt == qt) {
            #pragma unroll
            for (int i = 0; i < 4; i++)
                #pragma unroll
                for (int j = 0; j < 4; j++)
                    if (tx * 4 + j > ty * 4 + i) s[i][j] = -1e30f;
        }

        #pragma unroll
        for (int i = 0; i < 4; i++) {
            float rm = fmaxf(fmaxf(s[i][0], s[i][1]), fmaxf(s[i][2], s[i][3]));
            rm = fmaxf(rm, __shfl_xor_sync(0xffffffffu, rm, 8, 16));
            rm = fmaxf(rm, __shfl_xor_sync(0xffffffffu, rm, 4, 16));
            rm = fmaxf(rm, __shfl_xor_sync(0xffffffffu, rm, 2, 16));
            rm = fmaxf(rm, __shfl_xor_sync(0xffffffffu, rm, 1, 16));
            float mn = fmaxf(m_i[i], rm);
            float alpha = __expf(m_i[i] - mn);
            m_i[i] = mn;
            float rs = 0.0f;
            #pragma unroll
            for (int j = 0; j < 4; j++) {
                float p = __expf(s[i][j] - mn);
                s[i][j] = p;
                rs += p;
            }
            rs += __shfl_xor_sync(0xffffffffu, rs, 8, 16);
            rs += __shfl_xor_sync(0xffffffffu, rs, 4, 16);
            rs += __shfl_xor_sync(0xffffffffu, rs, 2, 16);
            rs += __shfl_xor_sync(0xffffffffu, rs, 1, 16);
            l_i[i] = l_i[i] * alpha + rs;
            #pragma unroll
            for (int j = 0; j < 4; j++) acc[i][j] *= alpha;
            int r = ty * 4 + i;
            Ps[r * 65 + tx * 4 + 0] = s[i][0];
            Ps[r * 65 + tx * 4 + 1] = s[i][1];
            Ps[r * 65 + tx * 4 + 2] = s[i][2];
            Ps[r * 65 + tx * 4 + 3] = s[i][3];
        }
        __syncwarp();

        #pragma unroll 8
        for (int c = 0; c < 64; c++) {
            float4 vv = *(const float4*)&Vs[c * 68 + tx * 4];
            float va[4] = {vv.x, vv.y, vv.z, vv.w};
            float p0 = Ps[(ty * 4 + 0) * 65 + c];
            float p1 = Ps[(ty * 4 + 1) * 65 + c];
            float p2 = Ps[(ty * 4 + 2) * 65 + c];
            float p3 = Ps[(ty * 4 + 3) * 65 + c];
            #pragma unroll
            for (int j = 0; j < 4; j++) {
                acc[0][j] = fmaf(p0, va[j], acc[0][j]);
                acc[1][j] = fmaf(p1, va[j], acc[1][j]);
                acc[2][j] = fmaf(p2, va[j], acc[2][j]);
                acc[3][j] = fmaf(p3, va[j], acc[3][j]);
            }
        }
    }

    #pragma unroll
    for (int i = 0; i < 4; i++) {
        float inv = 1.0f / l_i[i];
        float4 o4 = make_float4(acc[i][0] * inv, acc[i][1] * inv,
                                acc[i][2] * inv, acc[i][3] * inv);
        *(float4*)(Ob + (size_t)(qt * 64 + ty * 4 + i) * ld + tx * 4) = o4;
    }
}

// ---------------- launch ----------------
extern "C" void kernel_launch(void* const* d_in, const int* in_sizes, int n_in,
                              void* d_out, int out_size)
{
    const float* x       = (const float*)d_in[0];
    const float* w_q     = (const float*)d_in[1];
    const float* w_k     = (const float*)d_in[2];
    const float* w_v     = (const float*)d_in[3];
    const float* w_o     = (const float*)d_in[4];
    const float* alpha_p = (const float*)d_in[5];
    const float* delta_p = (const float*)d_in[6];
    const float* beta    = (const float*)d_in[7];
    const float* eta     = (const float*)d_in[8];
    const float* g1      = (const float*)d_in[9];
    const float* g2      = (const float*)d_in[10];
    const float* w_in    = (const float*)d_in[11];
    const float* b_in    = (const float*)d_in[12];
    const float* w_out   = (const float*)d_in[13];
    const float* b_out   = (const float*)d_in[14];
    float* out = (float*)d_out;

    float *xn, *y, *q, *k, *v, *ao, *x1, *xn2, *hb;
    cudaGetSymbolAddress((void**)&xn,  g_xn);
    cudaGetSymbolAddress((void**)&y,   g_y);
    cudaGetSymbolAddress((void**)&q,   g_q);
    cudaGetSymbolAddress((void**)&k,   g_k);
    cudaGetSymbolAddress((void**)&v,   g_v);
    cudaGetSymbolAddress((void**)&ao,  g_ao);
    cudaGetSymbolAddress((void**)&x1,  g_x1);
    cudaGetSymbolAddress((void**)&xn2, g_xn2);
    cudaGetSymbolAddress((void**)&hb,  g_hb);

    cudaFuncSetAttribute(attn_kernel, cudaFuncAttributeMaxDynamicSharedMemorySize,
                         ATTN_SMEM_BYTES);

    rmsnorm_kernel<<<BT, 256>>>(x, g1, xn);
    ema_kernel<<<(BB * DD * 16) / 256, 256>>>(xn, alpha_p, delta_p, beta, eta, y);

    dim3 gN1024(1024 / 128, BT / 128);
    tgemm_kernel<0><<<gN1024, 256>>>(y,  w_q, q, nullptr, nullptr, BT, 1024, 1024);
    tgemm_kernel<0><<<gN1024, 256>>>(y,  w_k, k, nullptr, nullptr, BT, 1024, 1024);
    tgemm_kernel<0><<<gN1024, 256>>>(xn, w_v, v, nullptr, nullptr, BT, 1024, 1024);

    rope_kernel<<<(BB * TT * HH * 16) / 256, 256>>>(q, k, v);

    attn_kernel<<<dim3(TT / 64, BB * HH), 256, ATTN_SMEM_BYTES>>>(q, k, v, ao);

    tgemm_kernel<1><<<gN1024, 256>>>(ao, w_o, x1, nullptr, x, BT, 1024, 1024);

    rmsnorm_kernel<<<BT, 256>>>(x1, g2, xn2);

    dim3 gN4096(4096 / 128, BT / 128);
    tgemm_kernel<2><<<gN4096, 256>>>(xn2, w_in, hb, b_in, nullptr, BT, 4096, 1024);
    tgemm_kernel<3><<<gN1024, 256>>>(hb, w_out, out, b_out, x1, BT, 1024, 4096);
}

// round 3
// speedup vs baseline: 2.4884x; 1.3847x over previous
#include <cuda_runtime.h>
#include <math.h>

#define BB 2
#define TT 2048
#define DD 1024
#define HH 16
#define HIDD 4096
#define BT (BB*TT)   // 4096 rows

// ---------------- scratch ----------------
__device__ float g_xn [BB*TT*DD];
__device__ float g_y  [BB*TT*DD];
__device__ float g_q  [BB*TT*DD];
__device__ float g_k  [BB*TT*DD];
__device__ float g_v  [BB*TT*DD];
__device__ float g_ao [BB*TT*DD];
__device__ float g_x1 [BB*TT*DD];
__device__ float g_xn2[BB*TT*DD];
__device__ float g_hb [BB*TT*HIDD];

// ---------------- helpers ----------------
__device__ __forceinline__ unsigned f2tf32(float x)
{
    unsigned r;
    asm("cvt.rna.tf32.f32 %0, %1;" : "=r"(r) : "f"(x));
    return r;
}
__device__ __forceinline__ float f2tf32f(float x) { return __uint_as_float(f2tf32(x)); }

__device__ __forceinline__ void ldmx4(unsigned& a0, unsigned& a1, unsigned& a2, unsigned& a3,
                                      unsigned addr)
{
    asm volatile("ldmatrix.sync.aligned.m8n8.x4.shared.b16 {%0,%1,%2,%3}, [%4];"
                 : "=r"(a0), "=r"(a1), "=r"(a2), "=r"(a3) : "r"(addr));
}
__device__ __forceinline__ void ldmx2(unsigned& a0, unsigned& a1, unsigned addr)
{
    asm volatile("ldmatrix.sync.aligned.m8n8.x2.shared.b16 {%0,%1}, [%2];"
                 : "=r"(a0), "=r"(a1) : "r"(addr));
}
__device__ __forceinline__ void mma_tf32(float* d, const unsigned* a, unsigned b0, unsigned b1)
{
    asm volatile(
        "mma.sync.aligned.m16n8k8.row.col.f32.tf32.tf32.f32 "
        "{%0,%1,%2,%3}, {%4,%5,%6,%7}, {%8,%9}, {%0,%1,%2,%3};\n"
        : "+f"(d[0]), "+f"(d[1]), "+f"(d[2]), "+f"(d[3])
        : "r"(a[0]), "r"(a[1]), "r"(a[2]), "r"(a[3]), "r"(b0), "r"(b1));
}

// ---------------- rmsnorm ----------------
__global__ void rmsnorm_kernel(const float* __restrict__ x, const float* __restrict__ g,
                               float* __restrict__ out)
{
    int row = blockIdx.x;
    int tid = threadIdx.x;
    const float4* xr = (const float4*)(x + (size_t)row * DD);
    float4 v = xr[tid];
    float s = v.x*v.x + v.y*v.y + v.z*v.z + v.w*v.w;
    #pragma unroll
    for (int o = 16; o; o >>= 1) s += __shfl_xor_sync(0xffffffffu, s, o);
    __shared__ float red[8];
    if ((tid & 31) == 0) red[tid >> 5] = s;
    __syncthreads();
    float tot = red[0]+red[1]+red[2]+red[3]+red[4]+red[5]+red[6]+red[7];
    float inv = rsqrtf(tot * (1.0f / (float)DD) + 1e-6f);
    const float4* gr = (const float4*)g;
    float4 gv = gr[tid];
    float4 o4;
    o4.x = gv.x * (v.x * inv);
    o4.y = gv.y * (v.y * inv);
    o4.z = gv.z * (v.z * inv);
    o4.w = gv.w * (v.w * inv);
    ((float4*)(out + (size_t)row * DD))[tid] = o4;
}

// ---------------- EMA scan ----------------
__global__ void ema_kernel(const float* __restrict__ xn,
                           const float* __restrict__ ap, const float* __restrict__ dp,
                           const float* __restrict__ beta, const float* __restrict__ eta,
                           float* __restrict__ y)
{
    int idx = blockIdx.x * blockDim.x + threadIdx.x;
    int n = idx & 15;
    int d = (idx >> 4) & (DD - 1);
    int b = idx >> 14;
    int dn = d * 16 + n;
    float a   = 1.0f / (1.0f + expf(-ap[dn]));
    float ddv = 1.0f / (1.0f + expf(-dp[dn]));
    float dec = 1.0f - a * ddv;
    float ab  = a * beta[dn];
    float et  = eta[dn];
    const float* xp = xn + (size_t)b * TT * DD + d;
    float* yp       = y  + (size_t)b * TT * DD + d;
    float h = 0.0f;
    for (int t = 0; t < TT; t++) {
        float u = xp[(size_t)t * DD];
        h = fmaf(dec, h, ab * u);
        float s = et * h;
        s += __shfl_xor_sync(0xffffffffu, s, 8, 16);
        s += __shfl_xor_sync(0xffffffffu, s, 4, 16);
        s += __shfl_xor_sync(0xffffffffu, s, 2, 16);
        s += __shfl_xor_sync(0xffffffffu, s, 1, 16);
        if (n == 0) yp[(size_t)t * DD] = s;
    }
}

// ---------------- RoPE ----------------
__global__ void rope_kernel(float* __restrict__ q, float* __restrict__ k, float* __restrict__ v)
{
    int idx = blockIdx.x * blockDim.x + threadIdx.x;
    int i = idx & 15;
    int h = (idx >> 4) & 15;
    int t = (idx >> 8) & (TT - 1);
    int b = idx >> 19;
    double fd = pow(10000.0, -(double)i / 16.0);
    float freq = (float)fd;
    float ang = (float)t * freq;
    double da = (double)ang;
    float c = (float)cos(da);
    float s = (float)sin(da);
    size_t base = ((size_t)(b * TT + t)) * DD + h * 64;
    {
        float x1 = q[base + i], x2 = q[base + 16 + i];
        q[base + i]      = x1 * c - x2 * s;
        q[base + 16 + i] = x2 * c + x1 * s;
    }
    {
        float x1 = k[base + i], x2 = k[base + 16 + i];
        k[base + i]      = x1 * c - x2 * s;
        k[base + 16 + i] = x2 * c + x1 * s;
    }
    {
        float x1 = v[base + i], x2 = v[base + 16 + i];
        v[base + i]      = x1 * c - x2 * s;
        v[base + 16 + i] = x2 * c + x1 * s;
    }
}

// ---------------- tf32 tensor-core GEMM 128x128x16, ldmatrix feed ----------------
__device__ __forceinline__ float gelu_tanh(float x)
{
    float x3 = x * x * x;
    float t = tanhf(0.7978845608028654f * (x + 0.044715f * x3));
    return 0.5f * x * (1.0f + t);
}

__device__ __forceinline__ float4 cvt4(float4 v)
{
    return make_float4(f2tf32f(v.x), f2tf32f(v.y), f2tf32f(v.z), f2tf32f(v.w));
}

// EPI: 0 = none, 1 = +resid, 2 = gelu(acc+bias), 3 = acc+bias+resid
template<int EPI>
__global__ __launch_bounds__(256)
void tgemm_kernel(const float* __restrict__ A, const float* __restrict__ B,
                  float* __restrict__ C, const float* __restrict__ bias,
                  const float* __restrict__ resid, int M, int N, int K)
{
    __shared__ float As[2][128][20];   // row-major A tile (tf32 bits), pad 20
    __shared__ float Bs[2][16][132];   // [k][n] (tf32 bits)

    const int tid  = threadIdx.x;
    const int bx = blockIdx.x, by = blockIdx.y;
    const int lane = tid & 31;
    const int warp = tid >> 5;
    const int wm = (warp & 1) * 64;
    const int wn = (warp >> 1) * 32;
    const int lr = lane >> 2;
    const int lc = lane & 3;
    const int lrow  = (lane & 7) + (lane & 8);   // ldmatrix source row within 16
    const int lkoff = (lane >> 4) * 4;           // ldmatrix k offset (floats)

    const int am = tid >> 2;
    const int ak = (tid & 3) << 2;
    const int bk = tid >> 5;
    const int bn = (tid & 31) << 2;
    const float* Ap = A + (size_t)(by * 128 + am) * K + ak;
    const float* Bp = B + (size_t)bk * N + bx * 128 + bn;

    float4 a0g = *(const float4*)Ap;
    float4 a1g = *(const float4*)(Ap + (size_t)64 * K);
    float4 b0g = *(const float4*)Bp;
    float4 b1g = *(const float4*)(Bp + (size_t)8 * N);

    *(float4*)&As[0][am][ak]      = cvt4(a0g);
    *(float4*)&As[0][am + 64][ak] = cvt4(a1g);
    *(float4*)&Bs[0][bk][bn]      = cvt4(b0g);
    *(float4*)&Bs[0][bk + 8][bn]  = cvt4(b1g);
    __syncthreads();

    float acc[4][4][4];
    #pragma unroll
    for (int mt = 0; mt < 4; mt++)
        #pragma unroll
        for (int nt = 0; nt < 4; nt++)
            #pragma unroll
            for (int r = 0; r < 4; r++) acc[mt][nt][r] = 0.0f;

    for (int k0 = 0; k0 < K; k0 += 16) {
        const int cb = (k0 >> 4) & 1;
        const bool has_next = (k0 + 16) < K;
        if (has_next) {
            Ap += 16;
            Bp += (size_t)16 * N;
            a0g = *(const float4*)Ap;
            a1g = *(const float4*)(Ap + (size_t)64 * K);
            b0g = *(const float4*)Bp;
            b1g = *(const float4*)(Bp + (size_t)8 * N);
        }

        #pragma unroll
        for (int kb = 0; kb < 2; kb++) {
            unsigned af[4][4];
            #pragma unroll
            for (int mt = 0; mt < 4; mt++) {
                unsigned addr = (unsigned)__cvta_generic_to_shared(
                    &As[cb][wm + mt * 16 + lrow][kb * 8 + lkoff]);
                ldmx4(af[mt][0], af[mt][1], af[mt][2], af[mt][3], addr);
            }
            unsigned bf[4][2];
            #pragma unroll
            for (int nt = 0; nt < 4; nt++) {
                int n = wn + nt * 8 + lr;
                bf[nt][0] = __float_as_uint(Bs[cb][kb * 8 + lc][n]);
                bf[nt][1] = __float_as_uint(Bs[cb][kb * 8 + lc + 4][n]);
            }
            #pragma unroll
            for (int mt = 0; mt < 4; mt++)
                #pragma unroll
                for (int nt = 0; nt < 4; nt++)
                    mma_tf32(acc[mt][nt], af[mt], bf[nt][0], bf[nt][1]);
        }

        if (has_next) {
            const int nb = cb ^ 1;
            *(float4*)&As[nb][am][ak]      = cvt4(a0g);
            *(float4*)&As[nb][am + 64][ak] = cvt4(a1g);
            *(float4*)&Bs[nb][bk][bn]      = cvt4(b0g);
            *(float4*)&Bs[nb][bk + 8][bn]  = cvt4(b1g);
        }
        __syncthreads();
    }

    #pragma unroll
    for (int mt = 0; mt < 4; mt++) {
        #pragma unroll
        for (int nt = 0; nt < 4; nt++) {
            int row = by * 128 + wm + mt * 16 + lr;
            int col = bx * 128 + wn + nt * 8 + 2 * lc;
            #pragma unroll
            for (int half = 0; half < 2; half++) {
                int r = row + half * 8;
                size_t off = (size_t)r * N + col;
                float v0 = acc[mt][nt][half * 2 + 0];
                float v1 = acc[mt][nt][half * 2 + 1];
                if (EPI == 2 || EPI == 3) { v0 += bias[col]; v1 += bias[col + 1]; }
                if (EPI == 2) { v0 = gelu_tanh(v0); v1 = gelu_tanh(v1); }
                if (EPI == 1 || EPI == 3) { v0 += resid[off]; v1 += resid[off + 1]; }
                *(float2*)(C + off) = make_float2(v0, v1);
            }
        }
    }
}

// ---------------- tf32 mma flash attention, BM=128, BN=64 ----------------
// smem layout (floats): Qs[128][68] | Ks[64][68] | Vs[64][68] (transposed) | Ps[128][68]
#define AT_QS 0
#define AT_KS (128*68)
#define AT_VS (192*68)
#define AT_PS (256*68)
#define ATTN_SMEM_BYTES (384*68*4)

__global__ __launch_bounds__(256, 1)
void attn_kernel(const float* __restrict__ Q, const float* __restrict__ Kk,
                 const float* __restrict__ V, float* __restrict__ O)
{
    extern __shared__ float sm[];

    const int qt = blockIdx.x;           // 128-row q tile
    const int bh = blockIdx.y;
    const int b = bh >> 4, h = bh & 15;
    const size_t ld = DD;
    const float* Qb = Q  + (size_t)b * TT * ld + h * 64;
    const float* Kb = Kk + (size_t)b * TT * ld + h * 64;
    const float* Vb = V  + (size_t)b * TT * ld + h * 64;
    float*       Ob = O  + (size_t)b * TT * ld + h * 64;

    const int tid  = threadIdx.x;
    const int lane = tid & 31;
    const int warp = tid >> 5;           // warp owns rows warp*16..+15
    const int lr = lane >> 2;
    const int lc = lane & 3;
    const int lrow  = (lane & 7) + (lane & 8);
    const int lkoff = (lane >> 4) * 4;

    // load Q tile: tf32-rounded, 1/sqrt(64) folded
    for (int i = tid; i < 128 * 16; i += 256) {
        int r = i >> 4, c4 = (i & 15) << 2;
        float4 qv = *(const float4*)(Qb + (size_t)(qt * 128 + r) * ld + c4);
        float4 o4 = make_float4(f2tf32f(qv.x * 0.125f), f2tf32f(qv.y * 0.125f),
                                f2tf32f(qv.z * 0.125f), f2tf32f(qv.w * 0.125f));
        *(float4*)&sm[AT_QS + r * 68 + c4] = o4;
    }

    float m_i[2] = {-1e30f, -1e30f};
    float l_i[2] = {0.0f, 0.0f};
    float o[8][4];
    #pragma unroll
    for (int nt = 0; nt < 8; nt++)
        #pragma unroll
        for (int r = 0; r < 4; r++) o[nt][r] = 0.0f;

    const int row_min = qt * 128 + warp * 16;
    const int nkt = 2 * qt + 2;

    for (int kt = 0; kt < nkt; kt++) {
        __syncthreads();    // previous K/V consumed (also covers Q store on first iter)
        // K tile natural [seq][dim]
        for (int i = tid; i < 64 * 16; i += 256) {
            int r = i >> 4, c4 = (i & 15) << 2;
            float4 kv = *(const float4*)(Kb + (size_t)(kt * 64 + r) * ld + c4);
            float4 o4 = make_float4(f2tf32f(kv.x), f2tf32f(kv.y), f2tf32f(kv.z), f2tf32f(kv.w));
            *(float4*)&sm[AT_KS + r * 68 + c4] = o4;
        }
        // V tile transposed [dim][seq] (conflict-free scatter: seq varies across lanes)
        for (int i = tid; i < 64 * 16; i += 256) {
            int r = i & 63;              // seq within tile
            int d4 = (i >> 6) << 2;      // dim group
            float4 vv = *(const float4*)(Vb + (size_t)(kt * 64 + r) * ld + d4);
            sm[AT_VS + (d4 + 0) * 68 + r] = f2tf32f(vv.x);
            sm[AT_VS + (d4 + 1) * 68 + r] = f2tf32f(vv.y);
            sm[AT_VS + (d4 + 2) * 68 + r] = f2tf32f(vv.z);
            sm[AT_VS + (d4 + 3) * 68 + r] = f2tf32f(vv.w);
        }
        __syncthreads();

        if (kt * 64 <= row_min + 15) {   // warp has at least one unmasked element
            // ---- S = Q K^T ----
            float s[8][4];
            #pragma unroll
            for (int nt = 0; nt < 8; nt++)
                #pragma unroll
                for (int r = 0; r < 4; r++) s[nt][r] = 0.0f;

            #pragma unroll
            for (int kb = 0; kb < 8; kb++) {
                unsigned af[4];
                unsigned qaddr = (unsigned)__cvta_generic_to_shared(
                    &sm[AT_QS + (warp * 16 + lrow) * 68 + kb * 8 + lkoff]);
                ldmx4(af[0], af[1], af[2], af[3], qaddr);
                #pragma unroll
                for (int nt = 0; nt < 8; nt++) {
                    unsigned b0, b1;
                    unsigned kaddr = (unsigned)__cvta_generic_to_shared(
                        &sm[AT_KS + (nt * 8 + (lane & 7)) * 68 + kb * 8 + ((lane >> 3) & 1) * 4]);
                    ldmx2(b0, b1, kaddr);
                    mma_tf32(s[nt], af, b0, b1);
                }
            }

            // causal mask (only tiles crossing the diagonal for this warp)
            if (kt * 64 + 63 > row_min) {
                #pragma unroll
                for (int nt = 0; nt < 8; nt++)
                    #pragma unroll
                    for (int r = 0; r < 4; r++) {
                        int col = kt * 64 + nt * 8 + 2 * lc + (r & 1);
                        int row = row_min + lr + 8 * (r >> 1);
                        if (col > row) s[nt][r] = -1e30f;
                    }
            }

            // ---- online softmax per row-half ----
            #pragma unroll
            for (int h2 = 0; h2 < 2; h2++) {
                float rm = -1e30f;
                #pragma unroll
                for (int nt = 0; nt < 8; nt++)
                    rm = fmaxf(rm, fmaxf(s[nt][2*h2], s[nt][2*h2+1]));
                rm = fmaxf(rm, __shfl_xor_sync(0xffffffffu, rm, 1));
                rm = fmaxf(rm, __shfl_xor_sync(0xffffffffu, rm, 2));
                float mn = fmaxf(m_i[h2], rm);
                float alpha = __expf(m_i[h2] - mn);
                m_i[h2] = mn;
                float rs = 0.0f;
                #pragma unroll
                for (int nt = 0; nt < 8; nt++) {
                    float p0 = __expf(s[nt][2*h2]   - mn);
                    float p1 = __expf(s[nt][2*h2+1] - mn);
                    s[nt][2*h2]   = p0;
                    s[nt][2*h2+1] = p1;
                    rs += p0 + p1;
                }
                rs += __shfl_xor_sync(0xffffffffu, rs, 1);
                rs += __shfl_xor_sync(0xffffffffu, rs, 2);
                l_i[h2] = l_i[h2] * alpha + rs;
                #pragma unroll
                for (int nt = 0; nt < 8; nt++) {
                    o[nt][2*h2]   *= alpha;
                    o[nt][2*h2+1] *= alpha;
                }
            }

            // ---- store P (tf32 bits) into warp-private Ps rows ----
            #pragma unroll
            for (int nt = 0; nt < 8; nt++)
                #pragma unroll
                for (int r = 0; r < 4; r++) {
                    int row = warp * 16 + lr + 8 * (r >> 1);
                    int col = nt * 8 + 2 * lc + (r & 1);
                    sm[AT_PS + row * 68 + col] = f2tf32f(s[nt][r]);
                }
            __syncwarp();

            // ---- O += P V ----
            #pragma unroll
            for (int kb = 0; kb < 8; kb++) {
                unsigned af[4];
                unsigned paddr = (unsigned)__cvta_generic_to_shared(
                    &sm[AT_PS + (warp * 16 + lrow) * 68 + kb * 8 + lkoff]);
                ldmx4(af[0], af[1], af[2], af[3], paddr);
                #pragma unroll
                for (int nt = 0; nt < 8; nt++) {
                    unsigned b0, b1;
                    unsigned vaddr = (unsigned)__cvta_generic_to_shared(
                        &sm[AT_VS + (nt * 8 + (lane & 7)) * 68 + kb * 8 + ((lane >> 3) & 1) * 4]);
                    ldmx2(b0, b1, vaddr);
                    mma_tf32(o[nt], af, b0, b1);
                }
            }
        }
    }

    // ---- write O ----
    #pragma unroll
    for (int h2 = 0; h2 < 2; h2++) {
        float inv = 1.0f / l_i[h2];
        int row = qt * 128 + warp * 16 + lr + 8 * h2;
        #pragma unroll
        for (int nt = 0; nt < 8; nt++) {
            int col = nt * 8 + 2 * lc;
            *(float2*)(Ob + (size_t)row * ld + col) =
                make_float2(o[nt][2*h2] * inv, o[nt][2*h2+1] * inv);
        }
    }
}

// ---------------- launch ----------------
extern "C" void kernel_launch(void* const* d_in, const int* in_sizes, int n_in,
                              void* d_out, int out_size)
{
    const float* x       = (const float*)d_in[0];
    const float* w_q     = (const float*)d_in[1];
    const float* w_k     = (const float*)d_in[2];
    const float* w_v     = (const float*)d_in[3];
    const float* w_o     = (const float*)d_in[4];
    const float* alpha_p = (const float*)d_in[5];
    const float* delta_p = (const float*)d_in[6];
    const float* beta    = (const float*)d_in[7];
    const float* eta     = (const float*)d_in[8];
    const float* g1      = (const float*)d_in[9];
    const float* g2      = (const float*)d_in[10];
    const float* w_in    = (const float*)d_in[11];
    const float* b_in    = (const float*)d_in[12];
    const float* w_out   = (const float*)d_in[13];
    const float* b_out   = (const float*)d_in[14];
    float* out = (float*)d_out;

    float *xn, *y, *q, *k, *v, *ao, *x1, *xn2, *hb;
    cudaGetSymbolAddress((void**)&xn,  g_xn);
    cudaGetSymbolAddress((void**)&y,   g_y);
    cudaGetSymbolAddress((void**)&q,   g_q);
    cudaGetSymbolAddress((void**)&k,   g_k);
    cudaGetSymbolAddress((void**)&v,   g_v);
    cudaGetSymbolAddress((void**)&ao,  g_ao);
    cudaGetSymbolAddress((void**)&x1,  g_x1);
    cudaGetSymbolAddress((void**)&xn2, g_xn2);
    cudaGetSymbolAddress((void**)&hb,  g_hb);

    cudaFuncSetAttribute(attn_kernel, cudaFuncAttributeMaxDynamicSharedMemorySize,
                         ATTN_SMEM_BYTES);

    rmsnorm_kernel<<<BT, 256>>>(x, g1, xn);
    ema_kernel<<<(BB * DD * 16) / 256, 256>>>(xn, alpha_p, delta_p, beta, eta, y);

    dim3 gN1024(1024 / 128, BT / 128);
    tgemm_kernel<0><<<gN1024, 256>>>(y,  w_q, q, nullptr, nullptr, BT, 1024, 1024);
    tgemm_kernel<0><<<gN1024, 256>>>(y,  w_k, k, nullptr, nullptr, BT, 1024, 1024);
    tgemm_kernel<0><<<gN1024, 256>>>(xn, w_v, v, nullptr, nullptr, BT, 1024, 1024);

    rope_kernel<<<(BB * TT * HH * 16) / 256, 256>>>(q, k, v);

    attn_kernel<<<dim3(TT / 128, BB * HH), 256, ATTN_SMEM_BYTES>>>(q, k, v, ao);

    tgemm_kernel<1><<<gN1024, 256>>>(ao, w_o, x1, nullptr, x, BT, 1024, 1024);

    rmsnorm_kernel<<<BT, 256>>>(x1, g2, xn2);

    dim3 gN4096(4096 / 128, BT / 128);
    tgemm_kernel<2><<<gN4096, 256>>>(xn2, w_in, hb, b_in, nullptr, BT, 4096, 1024);
    tgemm_kernel<3><<<gN1024, 256>>>(hb, w_out, out, b_out, x1, BT, 1024, 4096);
}

// round 4
// speedup vs baseline: 2.4937x; 1.0021x over previous
#include <cuda_runtime.h>
#include <math.h>

#define BB 2
#define TT 2048
#define DD 1024
#define HH 16
#define HIDD 4096
#define BT (BB*TT)   // 4096 rows

// ---------------- scratch ----------------
__device__ float g_xn [BB*TT*DD];
__device__ float g_y  [BB*TT*DD];
__device__ float g_q  [BB*TT*DD];
__device__ float g_k  [BB*TT*DD];
__device__ float g_v  [BB*TT*DD];
__device__ float g_ao [BB*TT*DD];
__device__ float g_x1 [BB*TT*DD];
__device__ float g_xn2[BB*TT*DD];
__device__ float g_hb [BB*TT*HIDD];

// ---------------- helpers ----------------
__device__ __forceinline__ unsigned f2tf32(float x)
{
    unsigned r;
    asm("cvt.rna.tf32.f32 %0, %1;" : "=r"(r) : "f"(x));
    return r;
}
__device__ __forceinline__ float f2tf32f(float x) { return __uint_as_float(f2tf32(x)); }

__device__ __forceinline__ void ldmx4(unsigned& a0, unsigned& a1, unsigned& a2, unsigned& a3,
                                      unsigned addr)
{
    asm volatile("ldmatrix.sync.aligned.m8n8.x4.shared.b16 {%0,%1,%2,%3}, [%4];"
                 : "=r"(a0), "=r"(a1), "=r"(a2), "=r"(a3) : "r"(addr));
}
__device__ __forceinline__ void ldmx2(unsigned& a0, unsigned& a1, unsigned addr)
{
    asm volatile("ldmatrix.sync.aligned.m8n8.x2.shared.b16 {%0,%1}, [%2];"
                 : "=r"(a0), "=r"(a1) : "r"(addr));
}
__device__ __forceinline__ void mma_tf32(float* d, const unsigned* a, unsigned b0, unsigned b1)
{
    asm volatile(
        "mma.sync.aligned.m16n8k8.row.col.f32.tf32.tf32.f32 "
        "{%0,%1,%2,%3}, {%4,%5,%6,%7}, {%8,%9}, {%0,%1,%2,%3};\n"
        : "+f"(d[0]), "+f"(d[1]), "+f"(d[2]), "+f"(d[3])
        : "r"(a[0]), "r"(a[1]), "r"(a[2]), "r"(a[3]), "r"(b0), "r"(b1));
}

// ---------------- rmsnorm ----------------
__global__ void rmsnorm_kernel(const float* __restrict__ x, const float* __restrict__ g,
                               float* __restrict__ out)
{
    int row = blockIdx.x;
    int tid = threadIdx.x;
    const float4* xr = (const float4*)(x + (size_t)row * DD);
    float4 v = xr[tid];
    float s = v.x*v.x + v.y*v.y + v.z*v.z + v.w*v.w;
    #pragma unroll
    for (int o = 16; o; o >>= 1) s += __shfl_xor_sync(0xffffffffu, s, o);
    __shared__ float red[8];
    if ((tid & 31) == 0) red[tid >> 5] = s;
    __syncthreads();
    float tot = red[0]+red[1]+red[2]+red[3]+red[4]+red[5]+red[6]+red[7];
    float inv = rsqrtf(tot * (1.0f / (float)DD) + 1e-6f);
    const float4* gr = (const float4*)g;
    float4 gv = gr[tid];
    float4 o4;
    o4.x = gv.x * (v.x * inv);
    o4.y = gv.y * (v.y * inv);
    o4.z = gv.z * (v.z * inv);
    o4.w = gv.w * (v.w * inv);
    ((float4*)(out + (size_t)row * DD))[tid] = o4;
}

// ---------------- EMA scan ----------------
__global__ void ema_kernel(const float* __restrict__ xn,
                           const float* __restrict__ ap, const float* __restrict__ dp,
                           const float* __restrict__ beta, const float* __restrict__ eta,
                           float* __restrict__ y)
{
    int idx = blockIdx.x * blockDim.x + threadIdx.x;
    int n = idx & 15;
    int d = (idx >> 4) & (DD - 1);
    int b = idx >> 14;
    int dn = d * 16 + n;
    float a   = 1.0f / (1.0f + expf(-ap[dn]));
    float ddv = 1.0f / (1.0f + expf(-dp[dn]));
    float dec = 1.0f - a * ddv;
    float ab  = a * beta[dn];
    float et  = eta[dn];
    const float* xp = xn + (size_t)b * TT * DD + d;
    float* yp       = y  + (size_t)b * TT * DD + d;
    float h = 0.0f;
    for (int t = 0; t < TT; t++) {
        float u = xp[(size_t)t * DD];
        h = fmaf(dec, h, ab * u);
        float s = et * h;
        s += __shfl_xor_sync(0xffffffffu, s, 8, 16);
        s += __shfl_xor_sync(0xffffffffu, s, 4, 16);
        s += __shfl_xor_sync(0xffffffffu, s, 2, 16);
        s += __shfl_xor_sync(0xffffffffu, s, 1, 16);
        if (n == 0) yp[(size_t)t * DD] = s;
    }
}

// ---------------- RoPE ----------------
__global__ void rope_kernel(float* __restrict__ q, float* __restrict__ k, float* __restrict__ v)
{
    int idx = blockIdx.x * blockDim.x + threadIdx.x;
    int i = idx & 15;
    int h = (idx >> 4) & 15;
    int t = (idx >> 8) & (TT - 1);
    int b = idx >> 19;
    double fd = pow(10000.0, -(double)i / 16.0);
    float freq = (float)fd;
    float ang = (float)t * freq;
    double da = (double)ang;
    float c = (float)cos(da);
    float s = (float)sin(da);
    size_t base = ((size_t)(b * TT + t)) * DD + h * 64;
    {
        float x1 = q[base + i], x2 = q[base + 16 + i];
        q[base + i]      = x1 * c - x2 * s;
        q[base + 16 + i] = x2 * c + x1 * s;
    }
    {
        float x1 = k[base + i], x2 = k[base + 16 + i];
        k[base + i]      = x1 * c - x2 * s;
        k[base + 16 + i] = x2 * c + x1 * s;
    }
    {
        float x1 = v[base + i], x2 = v[base + 16 + i];
        v[base + i]      = x1 * c - x2 * s;
        v[base + 16 + i] = x2 * c + x1 * s;
    }
}

// ---------------- tf32 tensor-core GEMM 128x128x16, ldmatrix feed ----------------
__device__ __forceinline__ float gelu_tanh(float x)
{
    float x3 = x * x * x;
    float t = tanhf(0.7978845608028654f * (x + 0.044715f * x3));
    return 0.5f * x * (1.0f + t);
}

__device__ __forceinline__ float4 cvt4(float4 v)
{
    return make_float4(f2tf32f(v.x), f2tf32f(v.y), f2tf32f(v.z), f2tf32f(v.w));
}

// EPI: 0 = none, 1 = +resid, 2 = gelu(acc+bias), 3 = acc+bias+resid
template<int EPI>
__global__ __launch_bounds__(256)
void tgemm_kernel(const float* __restrict__ A, const float* __restrict__ B,
                  float* __restrict__ C, const float* __restrict__ bias,
                  const float* __restrict__ resid, int M, int N, int K)
{
    __shared__ float As[2][128][20];   // row-major A tile (tf32 bits), pad 20
    __shared__ float Bs[2][16][132];   // [k][n] (tf32 bits)

    const int tid  = threadIdx.x;
    const int bx = blockIdx.x, by = blockIdx.y;
    const int lane = tid & 31;
    const int warp = tid >> 5;
    const int wm = (warp & 1) * 64;
    const int wn = (warp >> 1) * 32;
    const int lr = lane >> 2;
    const int lc = lane & 3;
    const int lrow  = (lane & 7) + (lane & 8);   // ldmatrix source row within 16
    const int lkoff = (lane >> 4) * 4;           // ldmatrix k offset (floats)

    const int am = tid >> 2;
    const int ak = (tid & 3) << 2;
    const int bk = tid >> 5;
    const int bn = (tid & 31) << 2;
    const float* Ap = A + (size_t)(by * 128 + am) * K + ak;
    const float* Bp = B + (size_t)bk * N + bx * 128 + bn;

    float4 a0g = *(const float4*)Ap;
    float4 a1g = *(const float4*)(Ap + (size_t)64 * K);
    float4 b0g = *(const float4*)Bp;
    float4 b1g = *(const float4*)(Bp + (size_t)8 * N);

    *(float4*)&As[0][am][ak]      = cvt4(a0g);
    *(float4*)&As[0][am + 64][ak] = cvt4(a1g);
    *(float4*)&Bs[0][bk][bn]      = cvt4(b0g);
    *(float4*)&Bs[0][bk + 8][bn]  = cvt4(b1g);
    __syncthreads();

    float acc[4][4][4];
    #pragma unroll
    for (int mt = 0; mt < 4; mt++)
        #pragma unroll
        for (int nt = 0; nt < 4; nt++)
            #pragma unroll
            for (int r = 0; r < 4; r++) acc[mt][nt][r] = 0.0f;

    for (int k0 = 0; k0 < K; k0 += 16) {
        const int cb = (k0 >> 4) & 1;
        const bool has_next = (k0 + 16) < K;
        if (has_next) {
            Ap += 16;
            Bp += (size_t)16 * N;
            a0g = *(const float4*)Ap;
            a1g = *(const float4*)(Ap + (size_t)64 * K);
            b0g = *(const float4*)Bp;
            b1g = *(const float4*)(Bp + (size_t)8 * N);
        }

        #pragma unroll
        for (int kb = 0; kb < 2; kb++) {
            unsigned af[4][4];
            #pragma unroll
            for (int mt = 0; mt < 4; mt++) {
                unsigned addr = (unsigned)__cvta_generic_to_shared(
                    &As[cb][wm + mt * 16 + lrow][kb * 8 + lkoff]);
                ldmx4(af[mt][0], af[mt][1], af[mt][2], af[mt][3], addr);
            }
            unsigned bf[4][2];
            #pragma unroll
            for (int nt = 0; nt < 4; nt++) {
                int n = wn + nt * 8 + lr;
                bf[nt][0] = __float_as_uint(Bs[cb][kb * 8 + lc][n]);
                bf[nt][1] = __float_as_uint(Bs[cb][kb * 8 + lc + 4][n]);
            }
            #pragma unroll
            for (int mt = 0; mt < 4; mt++)
                #pragma unroll
                for (int nt = 0; nt < 4; nt++)
                    mma_tf32(acc[mt][nt], af[mt], bf[nt][0], bf[nt][1]);
        }

        if (has_next) {
            const int nb = cb ^ 1;
            *(float4*)&As[nb][am][ak]      = cvt4(a0g);
            *(float4*)&As[nb][am + 64][ak] = cvt4(a1g);
            *(float4*)&Bs[nb][bk][bn]      = cvt4(b0g);
            *(float4*)&Bs[nb][bk + 8][bn]  = cvt4(b1g);
        }
        __syncthreads();
    }

    #pragma unroll
    for (int mt = 0; mt < 4; mt++) {
        #pragma unroll
        for (int nt = 0; nt < 4; nt++) {
            int row = by * 128 + wm + mt * 16 + lr;
            int col = bx * 128 + wn + nt * 8 + 2 * lc;
            #pragma unroll
            for (int half = 0; half < 2; half++) {
                int r = row + half * 8;
                size_t off = (size_t)r * N + col;
                float v0 = acc[mt][nt][half * 2 + 0];
                float v1 = acc[mt][nt][half * 2 + 1];
                if (EPI == 2 || EPI == 3) { v0 += bias[col]; v1 += bias[col + 1]; }
                if (EPI == 2) { v0 = gelu_tanh(v0); v1 = gelu_tanh(v1); }
                if (EPI == 1 || EPI == 3) { v0 += resid[off]; v1 += resid[off + 1]; }
                *(float2*)(C + off) = make_float2(v0, v1);
            }
        }
    }
}

// ---------------- tf32 mma flash attention, BM=128, BN=64 ----------------
// smem layout (floats): Qs[128][68] | Ks[64][68] | Vs[64][68] (transposed) | Ps[128][68]
#define AT_QS 0
#define AT_KS (128*68)
#define AT_VS (192*68)
#define AT_PS (256*68)
#define ATTN_SMEM_BYTES (384*68*4)

__global__ __launch_bounds__(256, 1)
void attn_kernel(const float* __restrict__ Q, const float* __restrict__ Kk,
                 const float* __restrict__ V, float* __restrict__ O)
{
    extern __shared__ float sm[];

    const int qt = blockIdx.x;           // 128-row q tile
    const int bh = blockIdx.y;
    const int b = bh >> 4, h = bh & 15;
    const size_t ld = DD;
    const float* Qb = Q  + (size_t)b * TT * ld + h * 64;
    const float* Kb = Kk + (size_t)b * TT * ld + h * 64;
    const float* Vb = V  + (size_t)b * TT * ld + h * 64;
    float*       Ob = O  + (size_t)b * TT * ld + h * 64;

    const int tid  = threadIdx.x;
    const int lane = tid & 31;
    const int warp = tid >> 5;           // warp owns rows warp*16..+15
    const int lr = lane >> 2;
    const int lc = lane & 3;
    const int lrow  = (lane & 7) + (lane & 8);
    const int lkoff = (lane >> 4) * 4;

    // load Q tile: tf32-rounded, 1/sqrt(64) folded
    for (int i = tid; i < 128 * 16; i += 256) {
        int r = i >> 4, c4 = (i & 15) << 2;
        float4 qv = *(const float4*)(Qb + (size_t)(qt * 128 + r) * ld + c4);
        float4 o4 = make_float4(f2tf32f(qv.x * 0.125f), f2tf32f(qv.y * 0.125f),
                                f2tf32f(qv.z * 0.125f), f2tf32f(qv.w * 0.125f));
        *(float4*)&sm[AT_QS + r * 68 + c4] = o4;
    }

    float m_i[2] = {-1e30f, -1e30f};
    float l_i[2] = {0.0f, 0.0f};
    float o[8][4];
    #pragma unroll
    for (int nt = 0; nt < 8; nt++)
        #pragma unroll
        for (int r = 0; r < 4; r++) o[nt][r] = 0.0f;

    const int row_min = qt * 128 + warp * 16;
    const int nkt = 2 * qt + 2;

    for (int kt = 0; kt < nkt; kt++) {
        __syncthreads();    // previous K/V consumed (also covers Q store on first iter)
        // K tile natural [seq][dim]
        for (int i = tid; i < 64 * 16; i += 256) {
            int r = i >> 4, c4 = (i & 15) << 2;
            float4 kv = *(const float4*)(Kb + (size_t)(kt * 64 + r) * ld + c4);
            float4 o4 = make_float4(f2tf32f(kv.x), f2tf32f(kv.y), f2tf32f(kv.z), f2tf32f(kv.w));
            *(float4*)&sm[AT_KS + r * 68 + c4] = o4;
        }
        // V tile transposed [dim][seq] (conflict-free scatter: seq varies across lanes)
        for (int i = tid; i < 64 * 16; i += 256) {
            int r = i & 63;              // seq within tile
            int d4 = (i >> 6) << 2;      // dim group
            float4 vv = *(const float4*)(Vb + (size_t)(kt * 64 + r) * ld + d4);
            sm[AT_VS + (d4 + 0) * 68 + r] = f2tf32f(vv.x);
            sm[AT_VS + (d4 + 1) * 68 + r] = f2tf32f(vv.y);
            sm[AT_VS + (d4 + 2) * 68 + r] = f2tf32f(vv.z);
            sm[AT_VS + (d4 + 3) * 68 + r] = f2tf32f(vv.w);
        }
        __syncthreads();

        if (kt * 64 <= row_min + 15) {   // warp has at least one unmasked element
            // ---- S = Q K^T ----
            float s[8][4];
            #pragma unroll
            for (int nt = 0; nt < 8; nt++)
                #pragma unroll
                for (int r = 0; r < 4; r++) s[nt][r] = 0.0f;

            #pragma unroll
            for (int kb = 0; kb < 8; kb++) {
                unsigned af[4];
                unsigned qaddr = (unsigned)__cvta_generic_to_shared(
                    &sm[AT_QS + (warp * 16 + lrow) * 68 + kb * 8 + lkoff]);
                ldmx4(af[0], af[1], af[2], af[3], qaddr);
                #pragma unroll
                for (int nt = 0; nt < 8; nt++) {
                    unsigned b0, b1;
                    unsigned kaddr = (unsigned)__cvta_generic_to_shared(
                        &sm[AT_KS + (nt * 8 + (lane & 7)) * 68 + kb * 8 + ((lane >> 3) & 1) * 4]);
                    ldmx2(b0, b1, kaddr);
                    mma_tf32(s[nt], af, b0, b1);
                }
            }

            // causal mask (only tiles crossing the diagonal for this warp)
            if (kt * 64 + 63 > row_min) {
                #pragma unroll
                for (int nt = 0; nt < 8; nt++)
                    #pragma unroll
                    for (int r = 0; r < 4; r++) {
                        int col = kt * 64 + nt * 8 + 2 * lc + (r & 1);
                        int row = row_min + lr + 8 * (r >> 1);
                        if (col > row) s[nt][r] = -1e30f;
                    }
            }

            // ---- online softmax per row-half ----
            #pragma unroll
            for (int h2 = 0; h2 < 2; h2++) {
                float rm = -1e30f;
                #pragma unroll
                for (int nt = 0; nt < 8; nt++)
                    rm = fmaxf(rm, fmaxf(s[nt][2*h2], s[nt][2*h2+1]));
                rm = fmaxf(rm, __shfl_xor_sync(0xffffffffu, rm, 1));
                rm = fmaxf(rm, __shfl_xor_sync(0xffffffffu, rm, 2));
                float mn = fmaxf(m_i[h2], rm);
                float alpha = __expf(m_i[h2] - mn);
                m_i[h2] = mn;
                float rs = 0.0f;
                #pragma unroll
                for (int nt = 0; nt < 8; nt++) {
                    float p0 = __expf(s[nt][2*h2]   - mn);
                    float p1 = __expf(s[nt][2*h2+1] - mn);
                    s[nt][2*h2]   = p0;
                    s[nt][2*h2+1] = p1;
                    rs += p0 + p1;
                }
                rs += __shfl_xor_sync(0xffffffffu, rs, 1);
                rs += __shfl_xor_sync(0xffffffffu, rs, 2);
                l_i[h2] = l_i[h2] * alpha + rs;
                #pragma unroll
                for (int nt = 0; nt < 8; nt++) {
                    o[nt][2*h2]   *= alpha;
                    o[nt][2*h2+1] *= alpha;
                }
            }

            // ---- store P (tf32 bits) into warp-private Ps rows ----
            #pragma unroll
            for (int nt = 0; nt < 8; nt++)
                #pragma unroll
                for (int r = 0; r < 4; r++) {
                    int row = warp * 16 + lr + 8 * (r >> 1);
                    int col = nt * 8 + 2 * lc + (r & 1);
                    sm[AT_PS + row * 68 + col] = f2tf32f(s[nt][r]);
                }
            __syncwarp();

            // ---- O += P V ----
            #pragma unroll
            for (int kb = 0; kb < 8; kb++) {
                unsigned af[4];
                unsigned paddr = (unsigned)__cvta_generic_to_shared(
                    &sm[AT_PS + (warp * 16 + lrow) * 68 + kb * 8 + lkoff]);
                ldmx4(af[0], af[1], af[2], af[3], paddr);
                #pragma unroll
                for (int nt = 0; nt < 8; nt++) {
                    unsigned b0, b1;
                    unsigned vaddr = (unsigned)__cvta_generic_to_shared(
                        &sm[AT_VS + (nt * 8 + (lane & 7)) * 68 + kb * 8 + ((lane >> 3) & 1) * 4]);
                    ldmx2(b0, b1, vaddr);
                    mma_tf32(o[nt], af, b0, b1);
                }
            }
        }
    }

    // ---- write O ----
    #pragma unroll
    for (int h2 = 0; h2 < 2; h2++) {
        float inv = 1.0f / l_i[h2];
        int row = qt * 128 + warp * 16 + lr + 8 * h2;
        #pragma unroll
        for (int nt = 0; nt < 8; nt++) {
            int col = nt * 8 + 2 * lc;
            *(float2*)(Ob + (size_t)row * ld + col) =
                make_float2(o[nt][2*h2] * inv, o[nt][2*h2+1] * inv);
        }
    }
}

// ---------------- launch ----------------
extern "C" void kernel_launch(void* const* d_in, const int* in_sizes, int n_in,
                              void* d_out, int out_size)
{
    const float* x       = (const float*)d_in[0];
    const float* w_q     = (const float*)d_in[1];
    const float* w_k     = (const float*)d_in[2];
    const float* w_v     = (const float*)d_in[3];
    const float* w_o     = (const float*)d_in[4];
    const float* alpha_p = (const float*)d_in[5];
    const float* delta_p = (const float*)d_in[6];
    const float* beta    = (const float*)d_in[7];
    const float* eta     = (const float*)d_in[8];
    const float* g1      = (const float*)d_in[9];
    const float* g2      = (const float*)d_in[10];
    const float* w_in    = (const float*)d_in[11];
    const float* b_in    = (const float*)d_in[12];
    const float* w_out   = (const float*)d_in[13];
    const float* b_out   = (const float*)d_in[14];
    float* out = (float*)d_out;

    float *xn, *y, *q, *k, *v, *ao, *x1, *xn2, *hb;
    cudaGetSymbolAddress((void**)&xn,  g_xn);
    cudaGetSymbolAddress((void**)&y,   g_y);
    cudaGetSymbolAddress((void**)&q,   g_q);
    cudaGetSymbolAddress((void**)&k,   g_k);
    cudaGetSymbolAddress((void**)&v,   g_v);
    cudaGetSymbolAddress((void**)&ao,  g_ao);
    cudaGetSymbolAddress((void**)&x1,  g_x1);
    cudaGetSymbolAddress((void**)&xn2, g_xn2);
    cudaGetSymbolAddress((void**)&hb,  g_hb);

    cudaFuncSetAttribute(attn_kernel, cudaFuncAttributeMaxDynamicSharedMemorySize,
                         ATTN_SMEM_BYTES);

    rmsnorm_kernel<<<BT, 256>>>(x, g1, xn);
    ema_kernel<<<(BB * DD * 16) / 256, 256>>>(xn, alpha_p, delta_p, beta, eta, y);

    dim3 gN1024(1024 / 128, BT / 128);
    tgemm_kernel<0><<<gN1024, 256>>>(y,  w_q, q, nullptr, nullptr, BT, 1024, 1024);
    tgemm_kernel<0><<<gN1024, 256>>>(y,  w_k, k, nullptr, nullptr, BT, 1024, 1024);
    tgemm_kernel<0><<<gN1024, 256>>>(xn, w_v, v, nullptr, nullptr, BT, 1024, 1024);

    rope_kernel<<<(BB * TT * HH * 16) / 256, 256>>>(q, k, v);

    attn_kernel<<<dim3(TT / 128, BB * HH), 256, ATTN_SMEM_BYTES>>>(q, k, v, ao);

    tgemm_kernel<1><<<gN1024, 256>>>(ao, w_o, x1, nullptr, x, BT, 1024, 1024);

    rmsnorm_kernel<<<BT, 256>>>(x1, g2, xn2);

    dim3 gN4096(4096 / 128, BT / 128);
    tgemm_kernel<2><<<gN4096, 256>>>(xn2, w_in, hb, b_in, nullptr, BT, 4096, 1024);
    tgemm_kernel<3><<<gN1024, 256>>>(hb, w_out, out, b_out, x1, BT, 1024, 4096);
}